// round 8
// baseline (speedup 1.0000x reference)
#include <cuda_runtime.h>
#include <cuda_bf16.h>
#include <cstdint>

// ---------------------------------------------------------------------------
// Problem constants
// ---------------------------------------------------------------------------
#define S_   128
#define B_   128
#define C_   256
#define E_   256
#define D_   512
#define EMB_ 256
#define V_   10000
#define T_   32
#define FEAT_ (D_ + 2*E_ + EMB_)   // 1280
#define VPAD_ 10240
#define KT_   3840                 // 3 * FEAT_

typedef unsigned long long ull;

// ---------------------------------------------------------------------------
// Scratch (__device__ globals; allocation-free)
// ---------------------------------------------------------------------------
__device__ float g_pre[S_ * B_ * 512];               // (S*B, 512) = [f|b]
__device__ float g_WhhT[2 * E_ * E_];
__device__ float g_enc_out[S_ * B_ * 2 * E_];
__device__ float g_enc_part[S_ * B_ * D_];
__device__ float g_hcat[B_ * 2 * E_];
__device__ float g_h[B_ * D_];
__device__ float g_gi_emb[T_ * B_ * 3 * D_];
__device__ float g_feat[T_ * B_ * FEAT_];
__device__ float g_p1[2 * B_ * 2048];                // split-K partials (gh|q)
__device__ float g_p2[2 * B_ * 1536];                // split-K partials (gi)
__device__ float g_bpre[512];

// global barrier state (zero-initialized at module load)
__device__ unsigned g_bar_arrive;
__device__ volatile unsigned g_bar_gen;

// split-bf16 operand buffers (triple layout)
__device__ __align__(16) __nv_bfloat16 g_A3[(size_t)(T_ * B_) * KT_];
__device__ __align__(16) __nv_bfloat16 g_B3[(size_t)VPAD_ * KT_];
__device__ __align__(16) __nv_bfloat16 gA3_src[(size_t)16384 * 768];
__device__ __align__(16) __nv_bfloat16 gB3_pre[512 * 768];
__device__ __align__(16) __nv_bfloat16 gA3_enc[(size_t)16384 * 1536];
__device__ __align__(16) __nv_bfloat16 gB3_attn[512 * 1536];
__device__ __align__(16) __nv_bfloat16 gA3_emb[4096 * 768];
__device__ __align__(16) __nv_bfloat16 gB3_wih[1536 * 768];

// ---------------------------------------------------------------------------
// helpers
// ---------------------------------------------------------------------------
__device__ __forceinline__ ull pk2(float lo, float hi) {
    ull r;
    asm("mov.b64 %0, {%1, %2};" : "=l"(r) : "f"(lo), "f"(hi));
    return r;
}
__device__ __forceinline__ void upk2(ull v, float& lo, float& hi) {
    asm("mov.b64 {%0, %1}, %2;" : "=f"(lo), "=f"(hi) : "l"(v));
}
__device__ __forceinline__ void fma2(ull& d, ull a, ull b) {
    asm("fma.rn.f32x2 %0, %1, %2, %0;" : "+l"(d) : "l"(a), "l"(b));
}
__device__ __forceinline__ uint32_t smem_u32(const void* p) {
    uint32_t a;
    asm("{ .reg .u64 t; cvta.to.shared.u64 t, %1; cvt.u32.u64 %0, t; }"
        : "=r"(a) : "l"(p));
    return a;
}

// ---------------------------------------------------------------------------
// split fp32 -> triple bf16.  mode 0 (A): [h | l | h]; mode 1 (B): [h | h | l]
// ---------------------------------------------------------------------------
__global__ __launch_bounds__(256) void split3_k(
    const float* __restrict__ src, int lda, int Kf, int realRows,
    __nv_bfloat16* __restrict__ dst, int mode)
{
    const int k = blockIdx.x * 256 + threadIdx.x;
    const int r = blockIdx.y;
    float x = (r < realRows) ? src[(size_t)r * lda + k] : 0.f;
    __nv_bfloat16 h = __float2bfloat16(x);
    __nv_bfloat16 l = __float2bfloat16(x - __bfloat162float(h));
    __nv_bfloat16* row = dst + (size_t)r * 3 * Kf;
    row[k] = h;
    row[Kf + k] = mode ? h : l;
    row[2 * Kf + k] = mode ? l : h;
}

__global__ __launch_bounds__(256) void splitB_pre_k(
    const float* __restrict__ Wf, const float* __restrict__ Wb)
{
    const int k = threadIdx.x;
    const int r = blockIdx.y;
    const float* W = (r < 256) ? Wf : Wb;
    float x = W[(size_t)(r & 255) * 256 + k];
    __nv_bfloat16 h = __float2bfloat16(x);
    __nv_bfloat16 l = __float2bfloat16(x - __bfloat162float(h));
    __nv_bfloat16* row = gB3_pre + (size_t)r * 768;
    row[k] = h;
    row[256 + k] = h;
    row[512 + k] = l;
}

__global__ void cat_bias_k(const float* __restrict__ a, const float* __restrict__ b)
{
    int i = blockIdx.x * 256 + threadIdx.x;
    g_bpre[i] = (i < 256) ? a[i] : b[i - 256];
}

// ---------------------------------------------------------------------------
// Split-bf16 HMMA GEMM v3: CTA 128(M) x 256(N), 256 threads,
// 8 warps as 2x4 grid of 64x64 warp tiles, 4-stage cp.async pipeline.
// flags: bit0 = tanh, bit1 = (b,t) scatter for logits.
// ---------------------------------------------------------------------------
#define L3 72                          // bf16 per smem row (144 B)
#define STG_A3 (128 * L3 * 2)          // 18432 B
#define STG4   ((128 + 256) * L3 * 2)  // 55296 B
#define HMMA_SMEM (4 * STG4)           // 221184 B

__global__ __launch_bounds__(256) void gemm_hmma(
    const __nv_bfloat16* __restrict__ A3, const __nv_bfloat16* __restrict__ B3,
    const float* __restrict__ bias, float* __restrict__ C,
    int ldc, int N, int K3, int flags)
{
    extern __shared__ __align__(16) char sm[];
    const uint32_t sbase = smem_u32(sm);
    const int tid = threadIdx.x, wid = tid >> 5, lane = tid & 31;
    const int m0 = blockIdx.y * 128, n0 = blockIdx.x * 256;
    const size_t ldk = (size_t)K3 * 64;

    const int lrow = tid >> 3;          // 0..31
    const int lcg  = tid & 7;
    const __nv_bfloat16* gA = A3 + (size_t)m0 * ldk;
    const __nv_bfloat16* gB = B3 + (size_t)n0 * ldk;

    float acc[4][8][4];
#pragma unroll
    for (int a = 0; a < 4; a++)
#pragma unroll
        for (int b = 0; b < 8; b++)
#pragma unroll
            for (int c = 0; c < 4; c++) acc[a][b][c] = 0.f;

    const int wr = wid >> 2, wc = wid & 3;        // 2 x 4 warp grid
    const int wm = wr * 64, wn = wc * 64;

    auto issue_stage = [&](int c, int buf) {
        uint32_t sa = sbase + buf * STG4;
        uint32_t sb = sa + STG_A3;
        size_t kof = (size_t)c * 64 + lcg * 8;
#pragma unroll
        for (int i = 0; i < 4; i++) {
            int row = lrow + i * 32;
            uint32_t da = sa + (uint32_t)(row * L3 + lcg * 8) * 2;
            const void* pa = gA + (size_t)row * ldk + kof;
            asm volatile("cp.async.cg.shared.global [%0], [%1], 16;"
                         :: "r"(da), "l"(pa));
        }
#pragma unroll
        for (int i = 0; i < 8; i++) {
            int row = lrow + i * 32;
            uint32_t db = sb + (uint32_t)(row * L3 + lcg * 8) * 2;
            const void* pb = gB + (size_t)row * ldk + kof;
            asm volatile("cp.async.cg.shared.global [%0], [%1], 16;"
                         :: "r"(db), "l"(pb));
        }
        asm volatile("cp.async.commit_group;" ::: "memory");
    };

    issue_stage(0, 0);
    issue_stage(1, 1);
    issue_stage(2, 2);

    int buf = 0;
    for (int c = 0; c < K3; c++) {
        if (c + 3 < K3) {
            issue_stage(c + 3, (buf + 3) & 3);
            asm volatile("cp.async.wait_group 3;" ::: "memory");
        } else {
            int rem = K3 - 1 - c;
            if (rem >= 2)      asm volatile("cp.async.wait_group 2;" ::: "memory");
            else if (rem == 1) asm volatile("cp.async.wait_group 1;" ::: "memory");
            else               asm volatile("cp.async.wait_group 0;" ::: "memory");
        }
        __syncthreads();

        const uint32_t sa  = sbase + buf * STG4;
        const uint32_t sbm = sa + STG_A3;

#pragma unroll
        for (int ks = 0; ks < 4; ks++) {
            uint32_t afr[4][4];
#pragma unroll
            for (int mt = 0; mt < 4; mt++) {
                int row = wm + mt * 16 + (lane & 15);
                int col = ks * 16 + ((lane >> 4) << 3);
                uint32_t addr = sa + (uint32_t)(row * L3 + col) * 2;
                asm volatile(
                    "ldmatrix.sync.aligned.m8n8.x4.shared.b16 {%0,%1,%2,%3}, [%4];"
                    : "=r"(afr[mt][0]), "=r"(afr[mt][1]),
                      "=r"(afr[mt][2]), "=r"(afr[mt][3])
                    : "r"(addr));
            }
#pragma unroll
            for (int half = 0; half < 2; half++) {
                uint32_t bfr[2][4];
#pragma unroll
                for (int j = 0; j < 2; j++) {
                    int nh = half * 2 + j;
                    int row = wn + nh * 16 + (lane & 7) + ((lane & 16) ? 8 : 0);
                    int col = ks * 16 + ((lane & 8) ? 8 : 0);
                    uint32_t addr = sbm + (uint32_t)(row * L3 + col) * 2;
                    asm volatile(
                        "ldmatrix.sync.aligned.m8n8.x4.shared.b16 {%0,%1,%2,%3}, [%4];"
                        : "=r"(bfr[j][0]), "=r"(bfr[j][1]),
                          "=r"(bfr[j][2]), "=r"(bfr[j][3])
                        : "r"(addr));
                }
#pragma unroll
                for (int mt = 0; mt < 4; mt++) {
#pragma unroll
                    for (int ntl = 0; ntl < 4; ntl++) {
                        int nt = half * 4 + ntl;
                        uint32_t b0 = bfr[ntl >> 1][(ntl & 1) * 2 + 0];
                        uint32_t b1 = bfr[ntl >> 1][(ntl & 1) * 2 + 1];
                        asm volatile(
                            "mma.sync.aligned.m16n8k16.row.col.f32.bf16.bf16.f32 "
                            "{%0,%1,%2,%3}, {%4,%5,%6,%7}, {%8,%9}, {%0,%1,%2,%3};"
                            : "+f"(acc[mt][nt][0]), "+f"(acc[mt][nt][1]),
                              "+f"(acc[mt][nt][2]), "+f"(acc[mt][nt][3])
                            : "r"(afr[mt][0]), "r"(afr[mt][1]),
                              "r"(afr[mt][2]), "r"(afr[mt][3]),
                              "r"(b0), "r"(b1));
                    }
                }
            }
        }
        __syncthreads();
        buf = (buf + 1) & 3;
    }

    // epilogue
    const int qr = lane >> 2, qc = (lane & 3) * 2;
#pragma unroll
    for (int mt = 0; mt < 4; mt++) {
        int mA = m0 + wm + mt * 16 + qr;
        int mB = mA + 8;
        int rA = (flags & 2) ? ((mA & (B_ - 1)) * T_ + (mA >> 7)) : mA;
        int rB = (flags & 2) ? ((mB & (B_ - 1)) * T_ + (mB >> 7)) : mB;
        float* C0 = C + (size_t)rA * ldc;
        float* C1 = C + (size_t)rB * ldc;
#pragma unroll
        for (int nt = 0; nt < 8; nt++) {
            int n = n0 + wn + nt * 8 + qc;
            if (n < N) {
                float bia0 = bias ? bias[n] : 0.f;
                float bia1 = bias ? bias[n + 1] : 0.f;
                float v0 = acc[mt][nt][0] + bia0;
                float v1 = acc[mt][nt][1] + bia1;
                float v2 = acc[mt][nt][2] + bia0;
                float v3 = acc[mt][nt][3] + bia1;
                if (flags & 1) {
                    v0 = tanhf(v0); v1 = tanhf(v1);
                    v2 = tanhf(v2); v3 = tanhf(v3);
                }
                C0[n] = v0; C0[n + 1] = v1;
                C1[n] = v2; C1[n + 1] = v3;
            }
        }
    }
}

// ---------------------------------------------------------------------------
// f32x2 GEMM (kept only for the tiny "hidden" projection)
// ---------------------------------------------------------------------------
__global__ __launch_bounds__(256) void gemm128(
    const float* __restrict__ A, int lda,
    const float* __restrict__ B, int ldb,
    const float* __restrict__ bias,
    float* __restrict__ C, int ldc,
    int N, int K, int flags)
{
    __shared__ __align__(16) float As[16][132];
    __shared__ __align__(16) float Bs[16][132];
    const int tid = threadIdx.x;
    const int m0 = blockIdx.y * 128;
    const int n0 = blockIdx.x * 128;
    const int tx = tid & 15, ty = tid >> 4;
    const int tm0 = ty * 8, tn0 = tx * 8;
    const int lr = tid >> 2;
    const int kq = (tid & 3) * 4;

    ull acc[8][4];
#pragma unroll
    for (int i = 0; i < 8; i++)
#pragma unroll
        for (int j = 0; j < 4; j++) acc[i][j] = 0ull;

    const float* Ap0 = A + (size_t)(m0 + lr) * lda + kq;
    const float* Ap1 = A + (size_t)(m0 + lr + 64) * lda + kq;
    const int nb0 = n0 + lr, nb1 = n0 + lr + 64;
    const float* Bp0 = B + (size_t)nb0 * ldb + kq;
    const float* Bp1 = B + (size_t)nb1 * ldb + kq;
    const bool v0 = nb0 < N, v1 = nb1 < N;
    const float4 z4 = make_float4(0.f, 0.f, 0.f, 0.f);

    float4 ra0 = *(const float4*)Ap0;
    float4 ra1 = *(const float4*)Ap1;
    float4 rb0 = v0 ? *(const float4*)Bp0 : z4;
    float4 rb1 = v1 ? *(const float4*)Bp1 : z4;

    for (int k0 = 0; k0 < K; k0 += 16) {
        __syncthreads();
        As[kq+0][lr] = ra0.x; As[kq+1][lr] = ra0.y;
        As[kq+2][lr] = ra0.z; As[kq+3][lr] = ra0.w;
        As[kq+0][lr+64] = ra1.x; As[kq+1][lr+64] = ra1.y;
        As[kq+2][lr+64] = ra1.z; As[kq+3][lr+64] = ra1.w;
        Bs[kq+0][lr] = rb0.x; Bs[kq+1][lr] = rb0.y;
        Bs[kq+2][lr] = rb0.z; Bs[kq+3][lr] = rb0.w;
        Bs[kq+0][lr+64] = rb1.x; Bs[kq+1][lr+64] = rb1.y;
        Bs[kq+2][lr+64] = rb1.z; Bs[kq+3][lr+64] = rb1.w;
        __syncthreads();
        if (k0 + 16 < K) {
            Ap0 += 16; Ap1 += 16; Bp0 += 16; Bp1 += 16;
            ra0 = *(const float4*)Ap0;
            ra1 = *(const float4*)Ap1;
            rb0 = v0 ? *(const float4*)Bp0 : z4;
            rb1 = v1 ? *(const float4*)Bp1 : z4;
        }
#pragma unroll
        for (int kk = 0; kk < 16; kk++) {
            float4 af0 = *(const float4*)&As[kk][tm0];
            float4 af1 = *(const float4*)&As[kk][tm0 + 4];
            ulonglong2 b01 = *(const ulonglong2*)&Bs[kk][tn0];
            ulonglong2 b23 = *(const ulonglong2*)&Bs[kk][tn0 + 4];
            const ull bp0 = b01.x, bp1 = b01.y, bp2 = b23.x, bp3 = b23.y;
            float av[8] = {af0.x, af0.y, af0.z, af0.w,
                           af1.x, af1.y, af1.z, af1.w};
#pragma unroll
            for (int i = 0; i < 8; i++) {
                ull ap = pk2(av[i], av[i]);
                fma2(acc[i][0], ap, bp0);
                fma2(acc[i][1], ap, bp1);
                fma2(acc[i][2], ap, bp2);
                fma2(acc[i][3], ap, bp3);
            }
        }
    }

#pragma unroll
    for (int i = 0; i < 8; i++) {
        int m = m0 + tm0 + i;
        float* Cp = C + (size_t)m * ldc;
#pragma unroll
        for (int j = 0; j < 4; j++) {
            float lo, hi; upk2(acc[i][j], lo, hi);
            int n = n0 + tn0 + 2 * j;
            if (n < N) {
                float v = lo + (bias ? bias[n] : 0.f);
                if (flags & 1) v = tanhf(v);
                Cp[n] = v;
            }
            if (n + 1 < N) {
                float v = hi + (bias ? bias[n + 1] : 0.f);
                if (flags & 1) v = tanhf(v);
                Cp[n + 1] = v;
            }
        }
    }
}

// ---------------------------------------------------------------------------
// Whh transpose
// ---------------------------------------------------------------------------
__global__ void transp_k(const float* __restrict__ Wf, const float* __restrict__ Wb)
{
    const int k = blockIdx.x, dir = blockIdx.y, e = threadIdx.x;
    const float* W = dir ? Wb : Wf;
    g_WhhT[dir * (E_*E_) + k * E_ + e] = W[e * E_ + k];
}

// ---------------------------------------------------------------------------
// Encoder recurrence  (pre layout: row-major (S*B, 512) = [f | b])
// ---------------------------------------------------------------------------
__global__ __launch_bounds__(256) void enc_rnn(
    const float* __restrict__ bhh_f, const float* __restrict__ bhh_b)
{
    __shared__ __align__(16) float hsh[E_ * 4];
    const int t = threadIdx.x;
    const int dir = blockIdx.y;
    const int b0 = blockIdx.x * 4;
    const float* WT = g_WhhT + dir * (E_*E_);
    const float* pre = g_pre + dir * E_;
    const float bias = dir ? bhh_b[t] : bhh_f[t];

#pragma unroll
    for (int b = 0; b < 4; b++) hsh[t * 4 + b] = 0.f;
    __syncthreads();

    float hcur[4] = {0.f, 0.f, 0.f, 0.f};
    for (int step = 0; step < S_; step++) {
        const int s = dir ? (S_ - 1 - step) : step;
        ull a01a = 0ull, a23a = 0ull, a01b = 0ull, a23b = 0ull;
        const float* wp = WT + t;
#pragma unroll 4
        for (int k = 0; k < E_; k += 2) {
            float w0 = __ldg(wp + (size_t)k * E_);
            float w1 = __ldg(wp + (size_t)(k + 1) * E_);
            ull h01_0 = *(const ull*)&hsh[k * 4];
            ull h23_0 = *(const ull*)&hsh[k * 4 + 2];
            ull h01_1 = *(const ull*)&hsh[(k + 1) * 4];
            ull h23_1 = *(const ull*)&hsh[(k + 1) * 4 + 2];
            ull w0p = pk2(w0, w0), w1p = pk2(w1, w1);
            fma2(a01a, h01_0, w0p);
            fma2(a23a, h23_0, w0p);
            fma2(a01b, h01_1, w1p);
            fma2(a23b, h23_1, w1p);
        }
        float r0, r1, r2, r3, s0, s1, s2, s3;
        upk2(a01a, r0, r1); upk2(a23a, r2, r3);
        upk2(a01b, s0, s1); upk2(a23b, s2, s3);
        float dot[4] = {r0 + s0, r1 + s1, r2 + s2, r3 + s3};
        __syncthreads();
#pragma unroll
        for (int b = 0; b < 4; b++) {
            int row = s * B_ + b0 + b;
            float h = tanhf(pre[(size_t)row * 512 + t] + dot[b] + bias);
            hcur[b] = h;
            hsh[t * 4 + b] = h;
            g_enc_out[(size_t)row * (2*E_) + dir * E_ + t] = h;
        }
        __syncthreads();
    }
#pragma unroll
    for (int b = 0; b < 4; b++)
        g_hcat[(size_t)(b0 + b) * (2*E_) + dir * E_ + t] = hcur[b];
}

// ---------------------------------------------------------------------------
// Embedding gather -> feat[..., 1024:1280]
// ---------------------------------------------------------------------------
__global__ void embed_k(const int* __restrict__ trg, const float* __restrict__ table)
{
    const int m = blockIdx.x;
    const int e = threadIdx.x;
    const int t = m >> 7, b = m & (B_ - 1);
    const int tok = trg[b * T_ + t];
    g_feat[(size_t)m * FEAT_ + (D_ + 2*E_) + e] = table[(size_t)tok * EMB_ + e];
}

// ---------------------------------------------------------------------------
// Persistent decoder: all 32 steps in one launch, 128 CTAs x 512 threads.
// Phases per step: P1 hq-GEMM -> P2 attention -> P3 gi-GEMM -> P4 GRU,
// separated by a global sense-reversing barrier (all CTAs resident: 128<148).
// ---------------------------------------------------------------------------
__device__ __forceinline__ void gridbar()
{
    __syncthreads();
    if (threadIdx.x == 0) {
        __threadfence();
        unsigned g = g_bar_gen;
        if (atomicAdd(&g_bar_arrive, 1u) == 127u) {
            g_bar_arrive = 0u;
            __threadfence();
            g_bar_gen = g + 1u;
        } else {
            while (g_bar_gen == g) __nanosleep(32);
        }
    }
    __syncthreads();
}

__global__ __launch_bounds__(512) void decoder_k(
    const float* __restrict__ Whh, const float* __restrict__ attnW,
    const float* __restrict__ Wih, const float* __restrict__ attn_v,
    const float* __restrict__ bhh, const float* __restrict__ bih)
{
    __shared__ __align__(16) float sbuf[16 * 132 + 16 * 36];
    float* As = sbuf;                   // [16][132]
    float* Bs = sbuf + 16 * 132;        // [16][36]
    const int bid = blockIdx.x;
    const int tid = threadIdx.x;
    const int w = tid >> 5, lane = tid & 31;

    for (int t = 0; t < T_; t++) {
        // ---- P1: [gh | q] = h @ [Whh ; W_h]^T, split-K=2, N tiles of 32 ----
        {
            const int n0 = (bid & 63) * 32;
            const int k0base = (bid >> 6) * 256;
            const int tm0 = (tid >> 3) * 2;          // 0..126
            const int tn0 = (tid & 7) * 4;           // 0..28
            const int alr = tid >> 2, akq = (tid & 3) * 4;
            const float* Ap = g_h + (size_t)alr * D_ + k0base + akq;
            const float* Bp = nullptr;
            int bnl = 0, bkq = 0;
            if (tid < 128) {
                bnl = tid >> 2; bkq = (tid & 3) * 4;
                int bn = n0 + bnl;
                Bp = (bn < 1536)
                    ? (Whh + (size_t)bn * D_ + k0base + bkq)
                    : (attnW + (size_t)(bn - 1536) * 1024 + k0base + bkq);
            }
            ull acc00 = 0, acc01 = 0, acc10 = 0, acc11 = 0;

            float4 ra = *(const float4*)Ap;
            float4 rb;
            if (tid < 128) rb = *(const float4*)Bp;

            for (int kc = 0; kc < 16; kc++) {
                __syncthreads();
                As[(akq+0)*132 + alr] = ra.x;
                As[(akq+1)*132 + alr] = ra.y;
                As[(akq+2)*132 + alr] = ra.z;
                As[(akq+3)*132 + alr] = ra.w;
                if (tid < 128) {
                    Bs[(bkq+0)*36 + bnl] = rb.x;
                    Bs[(bkq+1)*36 + bnl] = rb.y;
                    Bs[(bkq+2)*36 + bnl] = rb.z;
                    Bs[(bkq+3)*36 + bnl] = rb.w;
                }
                __syncthreads();
                if (kc < 15) {
                    Ap += 16;
                    ra = *(const float4*)Ap;
                    if (tid < 128) { Bp += 16; rb = *(const float4*)Bp; }
                }
#pragma unroll
                for (int kk = 0; kk < 16; kk++) {
                    float a0 = As[kk*132 + tm0];
                    float a1 = As[kk*132 + tm0 + 1];
                    ulonglong2 b = *(const ulonglong2*)&Bs[kk*36 + tn0];
                    ull ap0 = pk2(a0, a0), ap1 = pk2(a1, a1);
                    fma2(acc00, ap0, b.x); fma2(acc01, ap0, b.y);
                    fma2(acc10, ap1, b.x); fma2(acc11, ap1, b.y);
                }
            }
            float* P = g_p1 + (size_t)(bid >> 6) * (B_ * 2048);
            float lo, hi;
            float* Pp0 = P + (size_t)tm0 * 2048 + n0 + tn0;
            upk2(acc00, lo, hi); Pp0[0] = lo; Pp0[1] = hi;
            upk2(acc01, lo, hi); Pp0[2] = lo; Pp0[3] = hi;
            float* Pp1 = Pp0 + 2048;
            upk2(acc10, lo, hi); Pp1[0] = lo; Pp1[1] = hi;
            upk2(acc11, lo, hi); Pp1[2] = lo; Pp1[3] = hi;
        }
        gridbar();

        // ---- P2: attention (CTA = batch row) ----
        {
            float* qs = sbuf;           // [512]
            float* vs = sbuf + 512;     // [512]
            float* sc = sbuf + 1024;    // [128]
            const int b = bid;
            qs[tid] = g_p1[(size_t)b * 2048 + 1536 + tid]
                    + g_p1[(size_t)(B_ + b) * 2048 + 1536 + tid];
            vs[tid] = attn_v[tid];
            __syncthreads();

            const float4* qp = (const float4*)qs;
            const float4* vp = (const float4*)vs;
#pragma unroll
            for (int i = 0; i < 8; i++) {
                int s = w + i * 16;
                const float4* ep =
                    (const float4*)(g_enc_part + (size_t)(s * B_ + b) * D_);
                float acc = 0.f;
#pragma unroll
                for (int j = 0; j < 4; j++) {
                    int idx = lane + 32 * j;
                    float4 e = ep[idx]; float4 q = qp[idx]; float4 v = vp[idx];
                    acc += tanhf(e.x + q.x) * v.x + tanhf(e.y + q.y) * v.y
                         + tanhf(e.z + q.z) * v.z + tanhf(e.w + q.w) * v.w;
                }
#pragma unroll
                for (int o = 16; o; o >>= 1)
                    acc += __shfl_xor_sync(0xffffffffu, acc, o);
                if (lane == 0) sc[s] = acc;
            }
            __syncthreads();

            if (tid < 32) {
                float v[4]; float m = -1e30f;
#pragma unroll
                for (int i = 0; i < 4; i++) {
                    v[i] = sc[tid + 32 * i]; m = fmaxf(m, v[i]);
                }
#pragma unroll
                for (int o = 16; o; o >>= 1)
                    m = fmaxf(m, __shfl_xor_sync(0xffffffffu, m, o));
                float s = 0.f;
#pragma unroll
                for (int i = 0; i < 4; i++) { v[i] = expf(v[i] - m); s += v[i]; }
#pragma unroll
                for (int o = 16; o; o >>= 1)
                    s += __shfl_xor_sync(0xffffffffu, s, o);
                float inv = 1.f / s;
#pragma unroll
                for (int i = 0; i < 4; i++) sc[tid + 32 * i] = v[i] * inv;
            }
            __syncthreads();

            const float* eo = g_enc_out + (size_t)b * (2*E_) + tid;
            float acc = 0.f;
#pragma unroll 4
            for (int s = 0; s < S_; s++)
                acc += sc[s] * eo[(size_t)s * B_ * (2*E_)];
            g_feat[((size_t)t * B_ + b) * FEAT_ + D_ + tid] = acc;
        }
        gridbar();

        // ---- P3: gi = weighted @ Wih[:, EMB:]^T, split-K=2, 96 units ----
        if (bid < 96) {
            const int n0 = (bid % 48) * 32;
            const int k0base = (bid / 48) * 256;
            const int tm0 = (tid >> 3) * 2;
            const int tn0 = (tid & 7) * 4;
            const int alr = tid >> 2, akq = (tid & 3) * 4;
            const float* Ap = g_feat + ((size_t)t * B_ + alr) * FEAT_ + D_
                              + k0base + akq;
            const float* Bp = nullptr;
            int bnl = 0, bkq = 0;
            if (tid < 128) {
                bnl = tid >> 2; bkq = (tid & 3) * 4;
                Bp = Wih + (size_t)(n0 + bnl) * 768 + EMB_ + k0base + bkq;
            }
            ull acc00 = 0, acc01 = 0, acc10 = 0, acc11 = 0;

            float4 ra = *(const float4*)Ap;
            float4 rb;
            if (tid < 128) rb = *(const float4*)Bp;

            for (int kc = 0; kc < 16; kc++) {
                __syncthreads();
                As[(akq+0)*132 + alr] = ra.x;
                As[(akq+1)*132 + alr] = ra.y;
                As[(akq+2)*132 + alr] = ra.z;
                As[(akq+3)*132 + alr] = ra.w;
                if (tid < 128) {
                    Bs[(bkq+0)*36 + bnl] = rb.x;
                    Bs[(bkq+1)*36 + bnl] = rb.y;
                    Bs[(bkq+2)*36 + bnl] = rb.z;
                    Bs[(bkq+3)*36 + bnl] = rb.w;
                }
                __syncthreads();
                if (kc < 15) {
                    Ap += 16;
                    ra = *(const float4*)Ap;
                    if (tid < 128) { Bp += 16; rb = *(const float4*)Bp; }
                }
#pragma unroll
                for (int kk = 0; kk < 16; kk++) {
                    float a0 = As[kk*132 + tm0];
                    float a1 = As[kk*132 + tm0 + 1];
                    ulonglong2 b = *(const ulonglong2*)&Bs[kk*36 + tn0];
                    ull ap0 = pk2(a0, a0), ap1 = pk2(a1, a1);
                    fma2(acc00, ap0, b.x); fma2(acc01, ap0, b.y);
                    fma2(acc10, ap1, b.x); fma2(acc11, ap1, b.y);
                }
            }
            float* P = g_p2 + (size_t)(bid / 48) * (B_ * 1536);
            float lo, hi;
            float* Pp0 = P + (size_t)tm0 * 1536 + n0 + tn0;
            upk2(acc00, lo, hi); Pp0[0] = lo; Pp0[1] = hi;
            upk2(acc01, lo, hi); Pp0[2] = lo; Pp0[3] = hi;
            float* Pp1 = Pp0 + 1536;
            upk2(acc10, lo, hi); Pp1[0] = lo; Pp1[1] = hi;
            upk2(acc11, lo, hi); Pp1[2] = lo; Pp1[3] = hi;
        }
        gridbar();

        // ---- P4: GRU pointwise ----
        {
            const int b = bid, d = tid;
            const size_t m = (size_t)t * B_ + b;
            const float* p1a = g_p1 + (size_t)b * 2048;
            const float* p1b = g_p1 + (size_t)(B_ + b) * 2048;
            const float* p2a = g_p2 + (size_t)b * 1536;
            const float* p2b = g_p2 + (size_t)(B_ + b) * 1536;
            const float* ge = g_gi_emb + m * (3*D_);

            float gh_r = p1a[d] + p1b[d] + bhh[d];
            float gh_z = p1a[d + D_] + p1b[d + D_] + bhh[d + D_];
            float gh_n = p1a[d + 2*D_] + p1b[d + 2*D_] + bhh[d + 2*D_];
            float gi_r = p2a[d] + p2b[d] + bih[d];
            float gi_z = p2a[d + D_] + p2b[d + D_] + bih[d + D_];
            float gi_n = p2a[d + 2*D_] + p2b[d + 2*D_] + bih[d + 2*D_];

            float xr = gi_r + ge[d] + gh_r;
            float xz = gi_z + ge[d + D_] + gh_z;
            float gin = gi_n + ge[d + 2*D_];
            float r = 1.f / (1.f + expf(-xr));
            float z = 1.f / (1.f + expf(-xz));
            float n = tanhf(gin + r * gh_n);
            float hold = g_h[(size_t)b * D_ + d];
            float hnew = (1.f - z) * n + z * hold;
            g_h[(size_t)b * D_ + d] = hnew;
            g_feat[m * FEAT_ + d] = hnew;
        }
        gridbar();
    }
}

// ---------------------------------------------------------------------------
// Row softmax over V=10000
// ---------------------------------------------------------------------------
__global__ __launch_bounds__(512) void softmax_v_k(float* __restrict__ out)
{
    const int row = blockIdx.x;
    float* p = out + (size_t)row * V_;
    const int tid = threadIdx.x, lane = tid & 31, w = tid >> 5;
    __shared__ float red[16];
    __shared__ float bc;
    float m = -1e30f;
    for (int i = tid; i < V_; i += 512) m = fmaxf(m, p[i]);
#pragma unroll
    for (int o = 16; o; o >>= 1) m = fmaxf(m, __shfl_xor_sync(0xffffffffu, m, o));
    if (lane == 0) red[w] = m;
    __syncthreads();
    if (tid == 0) {
        float mm = red[0];
        for (int i = 1; i < 16; i++) mm = fmaxf(mm, red[i]);
        bc = mm;
    }
    __syncthreads();
    m = bc;
    float s = 0.f;
    for (int i = tid; i < V_; i += 512) { float e = expf(p[i] - m); p[i] = e; s += e; }
#pragma unroll
    for (int o = 16; o; o >>= 1) s += __shfl_xor_sync(0xffffffffu, s, o);
    if (lane == 0) red[w] = s;
    __syncthreads();
    if (tid == 0) {
        float ss = 0.f;
        for (int i = 0; i < 16; i++) ss += red[i];
        bc = 1.f / ss;
    }
    __syncthreads();
    float inv = bc;
    for (int i = tid; i < V_; i += 512) p[i] *= inv;
}

// ---------------------------------------------------------------------------
// Host orchestration
// ---------------------------------------------------------------------------
extern "C" void kernel_launch(void* const* d_in, const int* in_sizes, int n_in,
                              void* d_out, int out_size)
{
    const float* src       = (const float*)d_in[0];
    const int*   trg       = (const int*)  d_in[1];
    const float* Wih_f     = (const float*)d_in[2];
    const float* Whh_f     = (const float*)d_in[3];
    const float* bih_f     = (const float*)d_in[4];
    const float* bhh_f     = (const float*)d_in[5];
    const float* Wih_b     = (const float*)d_in[6];
    const float* Whh_b     = (const float*)d_in[7];
    const float* bih_b     = (const float*)d_in[8];
    const float* bhh_b     = (const float*)d_in[9];
    const float* fcW       = (const float*)d_in[10];
    const float* fcb       = (const float*)d_in[11];
    const float* attn_W    = (const float*)d_in[12];
    const float* attn_b    = (const float*)d_in[13];
    const float* attn_v    = (const float*)d_in[14];
    const float* emb_table = (const float*)d_in[15];
    const float* gru_Wih   = (const float*)d_in[16];
    const float* gru_Whh   = (const float*)d_in[17];
    const float* gru_bih   = (const float*)d_in[18];
    const float* gru_bhh   = (const float*)d_in[19];
    const float* out_W     = (const float*)d_in[20];
    const float* out_b     = (const float*)d_in[21];
    float* out = (float*)d_out;

    void *vp;
    cudaGetSymbolAddress(&vp, g_pre);      float* pre_p      = (float*)vp;
    cudaGetSymbolAddress(&vp, g_enc_out);  float* enc_out_p  = (float*)vp;
    cudaGetSymbolAddress(&vp, g_enc_part); float* enc_part_p = (float*)vp;
    cudaGetSymbolAddress(&vp, g_hcat);     float* hcat_p     = (float*)vp;
    cudaGetSymbolAddress(&vp, g_h);        float* h_p        = (float*)vp;
    cudaGetSymbolAddress(&vp, g_gi_emb);   float* gi_emb_p   = (float*)vp;
    cudaGetSymbolAddress(&vp, g_feat);     float* feat_p     = (float*)vp;
    cudaGetSymbolAddress(&vp, g_bpre);     float* bpre_p     = (float*)vp;
    cudaGetSymbolAddress(&vp, g_A3);       __nv_bfloat16* A3_p    = (__nv_bfloat16*)vp;
    cudaGetSymbolAddress(&vp, g_B3);       __nv_bfloat16* B3_p    = (__nv_bfloat16*)vp;
    cudaGetSymbolAddress(&vp, gA3_src);    __nv_bfloat16* A3src_p = (__nv_bfloat16*)vp;
    cudaGetSymbolAddress(&vp, gB3_pre);    __nv_bfloat16* B3pre_p = (__nv_bfloat16*)vp;
    cudaGetSymbolAddress(&vp, gA3_enc);    __nv_bfloat16* A3enc_p = (__nv_bfloat16*)vp;
    cudaGetSymbolAddress(&vp, gB3_attn);   __nv_bfloat16* B3att_p = (__nv_bfloat16*)vp;
    cudaGetSymbolAddress(&vp, gA3_emb);    __nv_bfloat16* A3emb_p = (__nv_bfloat16*)vp;
    cudaGetSymbolAddress(&vp, gB3_wih);    __nv_bfloat16* B3wih_p = (__nv_bfloat16*)vp;

    cudaFuncSetAttribute(gemm_hmma,
                         cudaFuncAttributeMaxDynamicSharedMemorySize, HMMA_SMEM);

    // launch #4 (ncu capture target) = gemm_hmma(pre)
    cat_bias_k<<<2, 256>>>(bih_f, bih_b);
    splitB_pre_k<<<dim3(1, 512), 256>>>(Wih_f, Wih_b);
    split3_k<<<dim3(1, 16384), 256>>>(src, C_, 256, 16384, A3src_p, 0);
    // pre = src @ [Wih_f;Wih_b]^T + bias : (16384 x 512)
    gemm_hmma<<<dim3(2, 128), 256, HMMA_SMEM>>>(A3src_p, B3pre_p, bpre_p,
                                                pre_p, 512, 512, 12, 0);
    transp_k<<<dim3(256, 2), 256>>>(Whh_f, Whh_b);
    enc_rnn<<<dim3(32, 2), 256>>>(bhh_f, bhh_b);
    // hidden = tanh(hcat @ fcW^T + fcb)
    gemm128<<<dim3(4, 1), 256>>>(hcat_p, 2*E_, fcW, 2*E_, fcb,
                                 h_p, D_, D_, 2*E_, 1);
    // enc_part = enc_out @ W_e^T + attn_b
    split3_k<<<dim3(2, 16384), 256>>>(enc_out_p, 2*E_, 512, 16384, A3enc_p, 0);
    split3_k<<<dim3(2, 512), 256>>>(attn_W + D_, D_ + 2*E_, 512, 512, B3att_p, 1);
    gemm_hmma<<<dim3(2, 128), 256, HMMA_SMEM>>>(A3enc_p, B3att_p, attn_b,
                                                enc_part_p, 512, 512, 24, 0);
    // embeddings + gi_emb = emb @ Wih[:, :EMB]^T
    embed_k<<<T_ * B_, EMB_>>>(trg, emb_table);
    split3_k<<<dim3(1, 4096), 256>>>(feat_p + (D_ + 2*E_), FEAT_, 256, 4096,
                                     A3emb_p, 0);
    split3_k<<<dim3(1, 1536), 256>>>(gru_Wih, EMB_ + 2*E_, 256, 1536, B3wih_p, 1);
    gemm_hmma<<<dim3(6, 32), 256, HMMA_SMEM>>>(A3emb_p, B3wih_p,
                                               (const float*)nullptr,
                                               gi_emb_p, 3*D_, 3*D_, 12, 0);
    // out_W split (independent of decoder)
    split3_k<<<dim3(5, VPAD_), 256>>>(out_W, FEAT_, FEAT_, V_, B3_p, 1);

    // --- persistent decoder: one launch for all 32 steps ---
    decoder_k<<<128, 512>>>(gru_Whh, attn_W, gru_Wih, attn_v, gru_bhh, gru_bih);

    // --- feat split + HMMA logits GEMM + softmax ---
    split3_k<<<dim3(5, T_ * B_), 256>>>(feat_p, FEAT_, FEAT_, T_ * B_, A3_p, 0);
    gemm_hmma<<<dim3(VPAD_ / 256, (T_ * B_) / 128), 256, HMMA_SMEM>>>(
        A3_p, B3_p, out_b, out, V_, V_, 60, 2);
    softmax_v_k<<<T_ * B_, 512>>>(out);
}

// round 9
// speedup vs baseline: 1.1479x; 1.1479x over previous
#include <cuda_runtime.h>
#include <cuda_bf16.h>
#include <cstdint>

// ---------------------------------------------------------------------------
// Problem constants
// ---------------------------------------------------------------------------
#define S_   128
#define B_   128
#define C_   256
#define E_   256
#define D_   512
#define EMB_ 256
#define V_   10000
#define T_   32
#define FEAT_ (D_ + 2*E_ + EMB_)   // 1280
#define VPAD_ 10240

typedef unsigned long long ull;

// ---------------------------------------------------------------------------
// Scratch (__device__ globals; allocation-free)
// ---------------------------------------------------------------------------
__device__ float g_pre[S_ * B_ * 512];               // (S*B, 512) = [f|b]
__device__ float g_WhhT[2 * E_ * E_];
__device__ float g_enc_out[S_ * B_ * 2 * E_];
__device__ float g_enc_part[S_ * B_ * D_];
__device__ float g_hcat[B_ * 2 * E_];
__device__ float g_h[B_ * D_];
__device__ float g_gi_emb[T_ * B_ * 3 * D_];
__device__ float g_feat[T_ * B_ * FEAT_];
__device__ float g_p1[2 * B_ * 2048];                // split-K partials (gh|q)
__device__ float g_p2[2 * B_ * 1536];                // split-K partials (gi)
__device__ float g_bpre[512];

// factored split-bf16 operands: per row, K/32 blocks of [h(32)|l(32)]
// row stride = 2*Kf elements.
__device__ __align__(16) __nv_bfloat16 g_A2[(size_t)(T_ * B_) * 2560];
__device__ __align__(16) __nv_bfloat16 g_B2[(size_t)VPAD_ * 2560];
__device__ __align__(16) __nv_bfloat16 gA2_src[(size_t)16384 * 512];
__device__ __align__(16) __nv_bfloat16 gB2_pre[512 * 512];
__device__ __align__(16) __nv_bfloat16 gA2_enc[(size_t)16384 * 1024];
__device__ __align__(16) __nv_bfloat16 gB2_attn[512 * 1024];
__device__ __align__(16) __nv_bfloat16 gA2_emb[4096 * 512];
__device__ __align__(16) __nv_bfloat16 gB2_wih[1536 * 512];

// ---------------------------------------------------------------------------
// helpers
// ---------------------------------------------------------------------------
__device__ __forceinline__ ull pk2(float lo, float hi) {
    ull r;
    asm("mov.b64 %0, {%1, %2};" : "=l"(r) : "f"(lo), "f"(hi));
    return r;
}
__device__ __forceinline__ void upk2(ull v, float& lo, float& hi) {
    asm("mov.b64 {%0, %1}, %2;" : "=f"(lo), "=f"(hi) : "l"(v));
}
__device__ __forceinline__ void fma2(ull& d, ull a, ull b) {
    asm("fma.rn.f32x2 %0, %1, %2, %0;" : "+l"(d) : "l"(a), "l"(b));
}
__device__ __forceinline__ uint32_t smem_u32(const void* p) {
    uint32_t a;
    asm("{ .reg .u64 t; cvta.to.shared.u64 t, %1; cvt.u32.u64 %0, t; }"
        : "=r"(a) : "l"(p));
    return a;
}

// ---------------------------------------------------------------------------
// split fp32 -> factored bf16 [h(32)|l(32)] per 32-element K block.
// grid: x = Kf/256, y = padded rows; zero-fill past realRows.
// ---------------------------------------------------------------------------
__global__ __launch_bounds__(256) void split2_k(
    const float* __restrict__ src, int lda, int Kf, int realRows,
    __nv_bfloat16* __restrict__ dst)
{
    const int k = blockIdx.x * 256 + threadIdx.x;
    const int r = blockIdx.y;
    float x = (r < realRows) ? src[(size_t)r * lda + k] : 0.f;
    __nv_bfloat16 h = __float2bfloat16(x);
    __nv_bfloat16 l = __float2bfloat16(x - __bfloat162float(h));
    size_t base = (size_t)r * 2 * Kf + (size_t)(k >> 5) * 64 + (k & 31);
    dst[base] = h;
    dst[base + 32] = l;
}

// dual-source variant for [Wih_f ; Wih_b], Kf=256
__global__ __launch_bounds__(256) void splitB2_pre_k(
    const float* __restrict__ Wf, const float* __restrict__ Wb)
{
    const int k = threadIdx.x;
    const int r = blockIdx.y;
    const float* W = (r < 256) ? Wf : Wb;
    float x = W[(size_t)(r & 255) * 256 + k];
    __nv_bfloat16 h = __float2bfloat16(x);
    __nv_bfloat16 l = __float2bfloat16(x - __bfloat162float(h));
    size_t base = (size_t)r * 512 + (size_t)(k >> 5) * 64 + (k & 31);
    gB2_pre[base] = h;
    gB2_pre[base + 32] = l;
}

__global__ void cat_bias_k(const float* __restrict__ a, const float* __restrict__ b)
{
    int i = blockIdx.x * 256 + threadIdx.x;
    g_bpre[i] = (i < 256) ? a[i] : b[i - 256];
}

// ---------------------------------------------------------------------------
// Factored split-bf16 HMMA GEMM:
//   C[row(m), n] = sum_{k<NCH*32} A[m,k]*B[n,k] + bias[n]  (fp32-split bf16)
// CTA 128x128, 256 threads, 8 warps of 64x32, 3-stage cp.async pipeline.
// Each stage covers K=32 holding Ah,Al,Bh,Bl (rows = [h32|l32], 144B stride).
// Per k16 step: acc += Ah*Bh + Al*Bh + Ah*Bl  (drops Al*Bl, ~2^-18 rel).
// flags: bit0 = tanh, bit1 = (b,t) scatter for logits.
// ---------------------------------------------------------------------------
#define L3 72                          // bf16 per smem row (144 B)
#define HSTG_A (128 * L3 * 2)          // 18432 B
#define HSTG   (2 * HSTG_A)            // 36864 B (A + B)
#define HMMA_SMEM (3 * HSTG)           // 110592 B

__global__ __launch_bounds__(256, 2) void gemm_hmma(
    const __nv_bfloat16* __restrict__ A2, const __nv_bfloat16* __restrict__ B2,
    const float* __restrict__ bias, float* __restrict__ C,
    int ldc, int N, int NCH, int flags)
{
    extern __shared__ __align__(16) char sm[];
    const uint32_t sbase = smem_u32(sm);
    const int tid = threadIdx.x, wid = tid >> 5, lane = tid & 31;
    const int m0 = blockIdx.y * 128, n0 = blockIdx.x * 128;
    const size_t ldk = (size_t)NCH * 64;     // elements per row

    const int lrow = tid >> 3;          // 0..31
    const int lcg  = tid & 7;           // 16B group within 128B row
    const __nv_bfloat16* gA = A2 + (size_t)m0 * ldk;
    const __nv_bfloat16* gB = B2 + (size_t)n0 * ldk;

    float acc[4][4][4];
#pragma unroll
    for (int a = 0; a < 4; a++)
#pragma unroll
        for (int b = 0; b < 4; b++)
#pragma unroll
            for (int c = 0; c < 4; c++) acc[a][b][c] = 0.f;

    const int wr = wid >> 2, wc = wid & 3;
    const int wm = wr * 64, wn = wc * 32;

    // stage fill: A rows 128 x 128B ([h|l]) + B rows 128 x 128B
    auto issue_stage = [&](int c, int buf) {
        uint32_t sa = sbase + buf * HSTG;
        uint32_t sb = sa + HSTG_A;
        size_t kof = (size_t)c * 64 + lcg * 8;
#pragma unroll
        for (int i = 0; i < 4; i++) {
            int row = lrow + i * 32;
            uint32_t da = sa + (uint32_t)(row * L3 + lcg * 8) * 2;
            const void* pa = gA + (size_t)row * ldk + kof;
            asm volatile("cp.async.cg.shared.global [%0], [%1], 16;"
                         :: "r"(da), "l"(pa));
            uint32_t db = sb + (uint32_t)(row * L3 + lcg * 8) * 2;
            const void* pb = gB + (size_t)row * ldk + kof;
            asm volatile("cp.async.cg.shared.global [%0], [%1], 16;"
                         :: "r"(db), "l"(pb));
        }
        asm volatile("cp.async.commit_group;" ::: "memory");
    };

    issue_stage(0, 0);
    issue_stage(1, 1);

    int buf = 0;
    for (int c = 0; c < NCH; c++) {
        if (c + 2 < NCH) {
            int nb = buf + 2; if (nb >= 3) nb -= 3;
            issue_stage(c + 2, nb);
            asm volatile("cp.async.wait_group 2;" ::: "memory");
        } else if (c + 1 < NCH) {
            asm volatile("cp.async.wait_group 1;" ::: "memory");
        } else {
            asm volatile("cp.async.wait_group 0;" ::: "memory");
        }
        __syncthreads();

        const uint32_t sa  = sbase + buf * HSTG;
        const uint32_t sbm = sa + HSTG_A;

#pragma unroll
        for (int ks = 0; ks < 2; ks++) {
            const int acol = ks * 16 + ((lane >> 4) << 3);
            const int bcol = ks * 16 + ((lane & 8) ? 8 : 0);
            uint32_t afh[4][4], afl[4][4];
#pragma unroll
            for (int mt = 0; mt < 4; mt++) {
                int row = wm + mt * 16 + (lane & 15);
                uint32_t ah = sa + (uint32_t)(row * L3 + acol) * 2;
                asm volatile(
                    "ldmatrix.sync.aligned.m8n8.x4.shared.b16 {%0,%1,%2,%3}, [%4];"
                    : "=r"(afh[mt][0]), "=r"(afh[mt][1]),
                      "=r"(afh[mt][2]), "=r"(afh[mt][3])
                    : "r"(ah));
                asm volatile(
                    "ldmatrix.sync.aligned.m8n8.x4.shared.b16 {%0,%1,%2,%3}, [%4];"
                    : "=r"(afl[mt][0]), "=r"(afl[mt][1]),
                      "=r"(afl[mt][2]), "=r"(afl[mt][3])
                    : "r"(ah + 64));   // +32 elements = Al half
            }
            uint32_t bfr[2][4];
#pragma unroll
            for (int j = 0; j < 2; j++) {
                int row = wn + j * 16 + (lane & 7) + ((lane & 16) ? 8 : 0);
                uint32_t ad = sbm + (uint32_t)(row * L3 + bcol) * 2;
                asm volatile(
                    "ldmatrix.sync.aligned.m8n8.x4.shared.b16 {%0,%1,%2,%3}, [%4];"
                    : "=r"(bfr[j][0]), "=r"(bfr[j][1]),
                      "=r"(bfr[j][2]), "=r"(bfr[j][3])
                    : "r"(ad));
            }
            // acc += Ah*Bh + Al*Bh
#pragma unroll
            for (int mt = 0; mt < 4; mt++) {
#pragma unroll
                for (int nt = 0; nt < 4; nt++) {
                    uint32_t b0 = bfr[nt >> 1][(nt & 1) * 2 + 0];
                    uint32_t b1 = bfr[nt >> 1][(nt & 1) * 2 + 1];
                    asm volatile(
                        "mma.sync.aligned.m16n8k16.row.col.f32.bf16.bf16.f32 "
                        "{%0,%1,%2,%3}, {%4,%5,%6,%7}, {%8,%9}, {%0,%1,%2,%3};"
                        : "+f"(acc[mt][nt][0]), "+f"(acc[mt][nt][1]),
                          "+f"(acc[mt][nt][2]), "+f"(acc[mt][nt][3])
                        : "r"(afh[mt][0]), "r"(afh[mt][1]),
                          "r"(afh[mt][2]), "r"(afh[mt][3]),
                          "r"(b0), "r"(b1));
                    asm volatile(
                        "mma.sync.aligned.m16n8k16.row.col.f32.bf16.bf16.f32 "
                        "{%0,%1,%2,%3}, {%4,%5,%6,%7}, {%8,%9}, {%0,%1,%2,%3};"
                        : "+f"(acc[mt][nt][0]), "+f"(acc[mt][nt][1]),
                          "+f"(acc[mt][nt][2]), "+f"(acc[mt][nt][3])
                        : "r"(afl[mt][0]), "r"(afl[mt][1]),
                          "r"(afl[mt][2]), "r"(afl[mt][3]),
                          "r"(b0), "r"(b1));
                }
            }
            // Bl frags, acc += Ah*Bl
#pragma unroll
            for (int j = 0; j < 2; j++) {
                int row = wn + j * 16 + (lane & 7) + ((lane & 16) ? 8 : 0);
                uint32_t ad = sbm + (uint32_t)(row * L3 + 32 + bcol) * 2;
                asm volatile(
                    "ldmatrix.sync.aligned.m8n8.x4.shared.b16 {%0,%1,%2,%3}, [%4];"
                    : "=r"(bfr[j][0]), "=r"(bfr[j][1]),
                      "=r"(bfr[j][2]), "=r"(bfr[j][3])
                    : "r"(ad));
            }
#pragma unroll
            for (int mt = 0; mt < 4; mt++) {
#pragma unroll
                for (int nt = 0; nt < 4; nt++) {
                    uint32_t b0 = bfr[nt >> 1][(nt & 1) * 2 + 0];
                    uint32_t b1 = bfr[nt >> 1][(nt & 1) * 2 + 1];
                    asm volatile(
                        "mma.sync.aligned.m16n8k16.row.col.f32.bf16.bf16.f32 "
                        "{%0,%1,%2,%3}, {%4,%5,%6,%7}, {%8,%9}, {%0,%1,%2,%3};"
                        : "+f"(acc[mt][nt][0]), "+f"(acc[mt][nt][1]),
                          "+f"(acc[mt][nt][2]), "+f"(acc[mt][nt][3])
                        : "r"(afh[mt][0]), "r"(afh[mt][1]),
                          "r"(afh[mt][2]), "r"(afh[mt][3]),
                          "r"(b0), "r"(b1));
                }
            }
        }
        __syncthreads();
        if (++buf == 3) buf = 0;
    }

    // epilogue
    const int qr = lane >> 2, qc = (lane & 3) * 2;
#pragma unroll
    for (int mt = 0; mt < 4; mt++) {
        int mA = m0 + wm + mt * 16 + qr;
        int mB = mA + 8;
        int rA = (flags & 2) ? ((mA & (B_ - 1)) * T_ + (mA >> 7)) : mA;
        int rB = (flags & 2) ? ((mB & (B_ - 1)) * T_ + (mB >> 7)) : mB;
        float* C0 = C + (size_t)rA * ldc;
        float* C1 = C + (size_t)rB * ldc;
#pragma unroll
        for (int nt = 0; nt < 4; nt++) {
            int n = n0 + wn + nt * 8 + qc;
            if (n < N) {
                float bia0 = bias ? bias[n] : 0.f;
                float bia1 = bias ? bias[n + 1] : 0.f;
                float v0 = acc[mt][nt][0] + bia0;
                float v1 = acc[mt][nt][1] + bia1;
                float v2 = acc[mt][nt][2] + bia0;
                float v3 = acc[mt][nt][3] + bia1;
                if (flags & 1) {
                    v0 = tanhf(v0); v1 = tanhf(v1);
                    v2 = tanhf(v2); v3 = tanhf(v3);
                }
                C0[n] = v0; C0[n + 1] = v1;
                C1[n] = v2; C1[n + 1] = v3;
            }
        }
    }
}

// ---------------------------------------------------------------------------
// f32x2 GEMM (kept only for the tiny "hidden" projection)
// ---------------------------------------------------------------------------
__global__ __launch_bounds__(256) void gemm128(
    const float* __restrict__ A, int lda,
    const float* __restrict__ B, int ldb,
    const float* __restrict__ bias,
    float* __restrict__ C, int ldc,
    int N, int K, int flags)
{
    __shared__ __align__(16) float As[16][132];
    __shared__ __align__(16) float Bs[16][132];
    const int tid = threadIdx.x;
    const int m0 = blockIdx.y * 128;
    const int n0 = blockIdx.x * 128;
    const int tx = tid & 15, ty = tid >> 4;
    const int tm0 = ty * 8, tn0 = tx * 8;
    const int lr = tid >> 2;
    const int kq = (tid & 3) * 4;

    ull acc[8][4];
#pragma unroll
    for (int i = 0; i < 8; i++)
#pragma unroll
        for (int j = 0; j < 4; j++) acc[i][j] = 0ull;

    const float* Ap0 = A + (size_t)(m0 + lr) * lda + kq;
    const float* Ap1 = A + (size_t)(m0 + lr + 64) * lda + kq;
    const int nb0 = n0 + lr, nb1 = n0 + lr + 64;
    const float* Bp0 = B + (size_t)nb0 * ldb + kq;
    const float* Bp1 = B + (size_t)nb1 * ldb + kq;
    const bool v0 = nb0 < N, v1 = nb1 < N;
    const float4 z4 = make_float4(0.f, 0.f, 0.f, 0.f);

    float4 ra0 = *(const float4*)Ap0;
    float4 ra1 = *(const float4*)Ap1;
    float4 rb0 = v0 ? *(const float4*)Bp0 : z4;
    float4 rb1 = v1 ? *(const float4*)Bp1 : z4;

    for (int k0 = 0; k0 < K; k0 += 16) {
        __syncthreads();
        As[kq+0][lr] = ra0.x; As[kq+1][lr] = ra0.y;
        As[kq+2][lr] = ra0.z; As[kq+3][lr] = ra0.w;
        As[kq+0][lr+64] = ra1.x; As[kq+1][lr+64] = ra1.y;
        As[kq+2][lr+64] = ra1.z; As[kq+3][lr+64] = ra1.w;
        Bs[kq+0][lr] = rb0.x; Bs[kq+1][lr] = rb0.y;
        Bs[kq+2][lr] = rb0.z; Bs[kq+3][lr] = rb0.w;
        Bs[kq+0][lr+64] = rb1.x; Bs[kq+1][lr+64] = rb1.y;
        Bs[kq+2][lr+64] = rb1.z; Bs[kq+3][lr+64] = rb1.w;
        __syncthreads();
        if (k0 + 16 < K) {
            Ap0 += 16; Ap1 += 16; Bp0 += 16; Bp1 += 16;
            ra0 = *(const float4*)Ap0;
            ra1 = *(const float4*)Ap1;
            rb0 = v0 ? *(const float4*)Bp0 : z4;
            rb1 = v1 ? *(const float4*)Bp1 : z4;
        }
#pragma unroll
        for (int kk = 0; kk < 16; kk++) {
            float4 af0 = *(const float4*)&As[kk][tm0];
            float4 af1 = *(const float4*)&As[kk][tm0 + 4];
            ulonglong2 b01 = *(const ulonglong2*)&Bs[kk][tn0];
            ulonglong2 b23 = *(const ulonglong2*)&Bs[kk][tn0 + 4];
            const ull bp0 = b01.x, bp1 = b01.y, bp2 = b23.x, bp3 = b23.y;
            float av[8] = {af0.x, af0.y, af0.z, af0.w,
                           af1.x, af1.y, af1.z, af1.w};
#pragma unroll
            for (int i = 0; i < 8; i++) {
                ull ap = pk2(av[i], av[i]);
                fma2(acc[i][0], ap, bp0);
                fma2(acc[i][1], ap, bp1);
                fma2(acc[i][2], ap, bp2);
                fma2(acc[i][3], ap, bp3);
            }
        }
    }

#pragma unroll
    for (int i = 0; i < 8; i++) {
        int m = m0 + tm0 + i;
        float* Cp = C + (size_t)m * ldc;
#pragma unroll
        for (int j = 0; j < 4; j++) {
            float lo, hi; upk2(acc[i][j], lo, hi);
            int n = n0 + tn0 + 2 * j;
            if (n < N) {
                float v = lo + (bias ? bias[n] : 0.f);
                if (flags & 1) v = tanhf(v);
                Cp[n] = v;
            }
            if (n + 1 < N) {
                float v = hi + (bias ? bias[n + 1] : 0.f);
                if (flags & 1) v = tanhf(v);
                Cp[n + 1] = v;
            }
        }
    }
}

// ---------------------------------------------------------------------------
// Decoder GEMM 1 (fused gh + q, split-K)
// ---------------------------------------------------------------------------
__global__ __launch_bounds__(256) void dec_gemm_hq(
    const float* __restrict__ Whh, const float* __restrict__ attnW)
{
    __shared__ __align__(16) float As[16][132];
    __shared__ __align__(16) float Bs[16][36];
    const int tid = threadIdx.x;
    const int n0 = blockIdx.x * 32;
    const int k0base = blockIdx.y * 256;
    const int tx = tid & 7, ty = tid >> 3;
    const int tm0 = ty * 4, tn0 = tx * 4;
    const int alr = tid >> 1, akq = (tid & 1) * 8;
    const int bn = n0 + (tid >> 2), bkq = (tid & 3) * 4, bnl = tid >> 2;

    const float* Ap = g_h + (size_t)alr * D_ + k0base + akq;
    const float* Bp = (bn < 1536)
        ? (Whh + (size_t)bn * D_ + k0base + bkq)
        : (attnW + (size_t)(bn - 1536) * (D_ + 2*E_) + k0base + bkq);

    ull acc[4][2];
#pragma unroll
    for (int i = 0; i < 4; i++) { acc[i][0] = 0ull; acc[i][1] = 0ull; }

    float4 ra0 = *(const float4*)Ap;
    float4 ra1 = *(const float4*)(Ap + 4);
    float4 rb;
    if (tid < 128) rb = *(const float4*)Bp;

    for (int kc = 0; kc < 16; kc++) {
        __syncthreads();
        As[akq+0][alr] = ra0.x; As[akq+1][alr] = ra0.y;
        As[akq+2][alr] = ra0.z; As[akq+3][alr] = ra0.w;
        As[akq+4][alr] = ra1.x; As[akq+5][alr] = ra1.y;
        As[akq+6][alr] = ra1.z; As[akq+7][alr] = ra1.w;
        if (tid < 128) {
            Bs[bkq+0][bnl] = rb.x; Bs[bkq+1][bnl] = rb.y;
            Bs[bkq+2][bnl] = rb.z; Bs[bkq+3][bnl] = rb.w;
        }
        __syncthreads();
        if (kc < 15) {
            Ap += 16;
            ra0 = *(const float4*)Ap;
            ra1 = *(const float4*)(Ap + 4);
            if (tid < 128) { Bp += 16; rb = *(const float4*)Bp; }
        }
#pragma unroll
        for (int kk = 0; kk < 16; kk++) {
            float4 a = *(const float4*)&As[kk][tm0];
            ulonglong2 b = *(const ulonglong2*)&Bs[kk][tn0];
            float av[4] = {a.x, a.y, a.z, a.w};
#pragma unroll
            for (int i = 0; i < 4; i++) {
                ull ap = pk2(av[i], av[i]);
                fma2(acc[i][0], ap, b.x);
                fma2(acc[i][1], ap, b.y);
            }
        }
    }

    float* P = g_p1 + (size_t)blockIdx.y * (B_ * 2048);
#pragma unroll
    for (int i = 0; i < 4; i++) {
        float* Pp = P + (size_t)(tm0 + i) * 2048 + n0 + tn0;
#pragma unroll
        for (int j = 0; j < 2; j++) {
            float lo, hi; upk2(acc[i][j], lo, hi);
            Pp[2*j] = lo; Pp[2*j + 1] = hi;
        }
    }
}

// ---------------------------------------------------------------------------
// Decoder GEMM 2 (gi from weighted, split-K)
// ---------------------------------------------------------------------------
__global__ __launch_bounds__(256) void dec_gemm_gi(
    const float* __restrict__ Wih, int t_step)
{
    __shared__ __align__(16) float As[16][132];
    __shared__ __align__(16) float Bs[16][36];
    const int tid = threadIdx.x;
    const int n0 = blockIdx.x * 32;
    const int k0base = blockIdx.y * 256;
    const int tx = tid & 7, ty = tid >> 3;
    const int tm0 = ty * 4, tn0 = tx * 4;
    const int alr = tid >> 1, akq = (tid & 1) * 8;
    const int bn = n0 + (tid >> 2), bkq = (tid & 3) * 4, bnl = tid >> 2;

    const float* Ap = g_feat + ((size_t)t_step * B_ + alr) * FEAT_ + D_ + k0base + akq;
    const float* Bp = Wih + (size_t)bn * (EMB_ + 2*E_) + EMB_ + k0base + bkq;

    ull acc[4][2];
#pragma unroll
    for (int i = 0; i < 4; i++) { acc[i][0] = 0ull; acc[i][1] = 0ull; }

    float4 ra0 = *(const float4*)Ap;
    float4 ra1 = *(const float4*)(Ap + 4);
    float4 rb;
    if (tid < 128) rb = *(const float4*)Bp;

    for (int kc = 0; kc < 16; kc++) {
        __syncthreads();
        As[akq+0][alr] = ra0.x; As[akq+1][alr] = ra0.y;
        As[akq+2][alr] = ra0.z; As[akq+3][alr] = ra0.w;
        As[akq+4][alr] = ra1.x; As[akq+5][alr] = ra1.y;
        As[akq+6][alr] = ra1.z; As[akq+7][alr] = ra1.w;
        if (tid < 128) {
            Bs[bkq+0][bnl] = rb.x; Bs[bkq+1][bnl] = rb.y;
            Bs[bkq+2][bnl] = rb.z; Bs[bkq+3][bnl] = rb.w;
        }
        __syncthreads();
        if (kc < 15) {
            Ap += 16;
            ra0 = *(const float4*)Ap;
            ra1 = *(const float4*)(Ap + 4);
            if (tid < 128) { Bp += 16; rb = *(const float4*)Bp; }
        }
#pragma unroll
        for (int kk = 0; kk < 16; kk++) {
            float4 a = *(const float4*)&As[kk][tm0];
            ulonglong2 b = *(const ulonglong2*)&Bs[kk][tn0];
            float av[4] = {a.x, a.y, a.z, a.w};
#pragma unroll
            for (int i = 0; i < 4; i++) {
                ull ap = pk2(av[i], av[i]);
                fma2(acc[i][0], ap, b.x);
                fma2(acc[i][1], ap, b.y);
            }
        }
    }

    float* P = g_p2 + (size_t)blockIdx.y * (B_ * 1536);
#pragma unroll
    for (int i = 0; i < 4; i++) {
        float* Pp = P + (size_t)(tm0 + i) * 1536 + n0 + tn0;
#pragma unroll
        for (int j = 0; j < 2; j++) {
            float lo, hi; upk2(acc[i][j], lo, hi);
            Pp[2*j] = lo; Pp[2*j + 1] = hi;
        }
    }
}

// ---------------------------------------------------------------------------
// Whh transpose
// ---------------------------------------------------------------------------
__global__ void transp_k(const float* __restrict__ Wf, const float* __restrict__ Wb)
{
    const int k = blockIdx.x, dir = blockIdx.y, e = threadIdx.x;
    const float* W = dir ? Wb : Wf;
    g_WhhT[dir * (E_*E_) + k * E_ + e] = W[e * E_ + k];
}

// ---------------------------------------------------------------------------
// Encoder recurrence  (pre layout: row-major (S*B, 512) = [f | b])
// ---------------------------------------------------------------------------
__global__ __launch_bounds__(256) void enc_rnn(
    const float* __restrict__ bhh_f, const float* __restrict__ bhh_b)
{
    __shared__ __align__(16) float hsh[E_ * 4];
    const int t = threadIdx.x;
    const int dir = blockIdx.y;
    const int b0 = blockIdx.x * 4;
    const float* WT = g_WhhT + dir * (E_*E_);
    const float* pre = g_pre + dir * E_;
    const float bias = dir ? bhh_b[t] : bhh_f[t];

#pragma unroll
    for (int b = 0; b < 4; b++) hsh[t * 4 + b] = 0.f;
    __syncthreads();

    float hcur[4] = {0.f, 0.f, 0.f, 0.f};
    for (int step = 0; step < S_; step++) {
        const int s = dir ? (S_ - 1 - step) : step;
        ull a01a = 0ull, a23a = 0ull, a01b = 0ull, a23b = 0ull;
        const float* wp = WT + t;
#pragma unroll 4
        for (int k = 0; k < E_; k += 2) {
            float w0 = __ldg(wp + (size_t)k * E_);
            float w1 = __ldg(wp + (size_t)(k + 1) * E_);
            ull h01_0 = *(const ull*)&hsh[k * 4];
            ull h23_0 = *(const ull*)&hsh[k * 4 + 2];
            ull h01_1 = *(const ull*)&hsh[(k + 1) * 4];
            ull h23_1 = *(const ull*)&hsh[(k + 1) * 4 + 2];
            ull w0p = pk2(w0, w0), w1p = pk2(w1, w1);
            fma2(a01a, h01_0, w0p);
            fma2(a23a, h23_0, w0p);
            fma2(a01b, h01_1, w1p);
            fma2(a23b, h23_1, w1p);
        }
        float r0, r1, r2, r3, s0, s1, s2, s3;
        upk2(a01a, r0, r1); upk2(a23a, r2, r3);
        upk2(a01b, s0, s1); upk2(a23b, s2, s3);
        float dot[4] = {r0 + s0, r1 + s1, r2 + s2, r3 + s3};
        __syncthreads();
#pragma unroll
        for (int b = 0; b < 4; b++) {
            int row = s * B_ + b0 + b;
            float h = tanhf(pre[(size_t)row * 512 + t] + dot[b] + bias);
            hcur[b] = h;
            hsh[t * 4 + b] = h;
            g_enc_out[(size_t)row * (2*E_) + dir * E_ + t] = h;
        }
        __syncthreads();
    }
#pragma unroll
    for (int b = 0; b < 4; b++)
        g_hcat[(size_t)(b0 + b) * (2*E_) + dir * E_ + t] = hcur[b];
}

// ---------------------------------------------------------------------------
// Embedding gather -> feat[..., 1024:1280]
// ---------------------------------------------------------------------------
__global__ void embed_k(const int* __restrict__ trg, const float* __restrict__ table)
{
    const int m = blockIdx.x;
    const int e = threadIdx.x;
    const int t = m >> 7, b = m & (B_ - 1);
    const int tok = trg[b * T_ + t];
    g_feat[(size_t)m * FEAT_ + (D_ + 2*E_) + e] = table[(size_t)tok * EMB_ + e];
}

// ---------------------------------------------------------------------------
// Fused attention: q from split-K partials -> scores -> softmax -> weighted
// ---------------------------------------------------------------------------
__global__ __launch_bounds__(512) void attn_fused_k(
    const float* __restrict__ attn_v, int t_step)
{
    __shared__ __align__(16) float qs[D_];
    __shared__ __align__(16) float vs[D_];
    __shared__ float sc[S_];
    const int b = blockIdx.x;
    const int tid = threadIdx.x;
    const int w = tid >> 5, lane = tid & 31;

    qs[tid] = g_p1[(size_t)b * 2048 + 1536 + tid]
            + g_p1[(size_t)(B_ + b) * 2048 + 1536 + tid];
    vs[tid] = attn_v[tid];
    __syncthreads();

    const float4* qp = (const float4*)qs;
    const float4* vp = (const float4*)vs;
#pragma unroll
    for (int i = 0; i < 8; i++) {
        int s = w + i * 16;
        const float4* ep = (const float4*)(g_enc_part + (size_t)(s * B_ + b) * D_);
        float acc = 0.f;
#pragma unroll
        for (int j = 0; j < 4; j++) {
            int idx = lane + 32 * j;
            float4 e = ep[idx]; float4 q = qp[idx]; float4 v = vp[idx];
            acc += tanhf(e.x + q.x) * v.x + tanhf(e.y + q.y) * v.y
                 + tanhf(e.z + q.z) * v.z + tanhf(e.w + q.w) * v.w;
        }
#pragma unroll
        for (int o = 16; o; o >>= 1) acc += __shfl_xor_sync(0xffffffffu, acc, o);
        if (lane == 0) sc[s] = acc;
    }
    __syncthreads();

    if (tid < 32) {
        float v[4]; float m = -1e30f;
#pragma unroll
        for (int i = 0; i < 4; i++) { v[i] = sc[tid + 32 * i]; m = fmaxf(m, v[i]); }
#pragma unroll
        for (int o = 16; o; o >>= 1) m = fmaxf(m, __shfl_xor_sync(0xffffffffu, m, o));
        float s = 0.f;
#pragma unroll
        for (int i = 0; i < 4; i++) { v[i] = expf(v[i] - m); s += v[i]; }
#pragma unroll
        for (int o = 16; o; o >>= 1) s += __shfl_xor_sync(0xffffffffu, s, o);
        float inv = 1.f / s;
#pragma unroll
        for (int i = 0; i < 4; i++) sc[tid + 32 * i] = v[i] * inv;
    }
    __syncthreads();

    const int e = tid;
    const float* eo = g_enc_out + (size_t)b * (2*E_) + e;
    float acc = 0.f;
#pragma unroll 4
    for (int s = 0; s < S_; s++)
        acc += sc[s] * eo[(size_t)s * B_ * (2*E_)];
    g_feat[((size_t)t_step * B_ + b) * FEAT_ + D_ + e] = acc;
}

// ---------------------------------------------------------------------------
// GRU pointwise update (combines split-K partials + biases inline)
// ---------------------------------------------------------------------------
__global__ __launch_bounds__(512) void gru_k(int t_step,
    const float* __restrict__ bhh, const float* __restrict__ bih)
{
    const int b = blockIdx.x, d = threadIdx.x;
    const size_t m = (size_t)t_step * B_ + b;
    const float* p1a = g_p1 + (size_t)b * 2048;
    const float* p1b = g_p1 + (size_t)(B_ + b) * 2048;
    const float* p2a = g_p2 + (size_t)b * 1536;
    const float* p2b = g_p2 + (size_t)(B_ + b) * 1536;
    const float* ge = g_gi_emb + m * (3*D_);

    float gh_r = p1a[d] + p1b[d] + bhh[d];
    float gh_z = p1a[d + D_] + p1b[d + D_] + bhh[d + D_];
    float gh_n = p1a[d + 2*D_] + p1b[d + 2*D_] + bhh[d + 2*D_];
    float gi_r = p2a[d] + p2b[d] + bih[d];
    float gi_z = p2a[d + D_] + p2b[d + D_] + bih[d + D_];
    float gi_n = p2a[d + 2*D_] + p2b[d + 2*D_] + bih[d + 2*D_];

    float xr = gi_r + ge[d] + gh_r;
    float xz = gi_z + ge[d + D_] + gh_z;
    float gin = gi_n + ge[d + 2*D_];
    float r = 1.f / (1.f + expf(-xr));
    float z = 1.f / (1.f + expf(-xz));
    float n = tanhf(gin + r * gh_n);
    float hold = g_h[(size_t)b * D_ + d];
    float hnew = (1.f - z) * n + z * hold;
    g_h[(size_t)b * D_ + d] = hnew;
    g_feat[m * FEAT_ + d] = hnew;
}

// ---------------------------------------------------------------------------
// Row softmax over V=10000
// ---------------------------------------------------------------------------
__global__ __launch_bounds__(512) void softmax_v_k(float* __restrict__ out)
{
    const int row = blockIdx.x;
    float* p = out + (size_t)row * V_;
    const int tid = threadIdx.x, lane = tid & 31, w = tid >> 5;
    __shared__ float red[16];
    __shared__ float bc;
    float m = -1e30f;
    for (int i = tid; i < V_; i += 512) m = fmaxf(m, p[i]);
#pragma unroll
    for (int o = 16; o; o >>= 1) m = fmaxf(m, __shfl_xor_sync(0xffffffffu, m, o));
    if (lane == 0) red[w] = m;
    __syncthreads();
    if (tid == 0) {
        float mm = red[0];
        for (int i = 1; i < 16; i++) mm = fmaxf(mm, red[i]);
        bc = mm;
    }
    __syncthreads();
    m = bc;
    float s = 0.f;
    for (int i = tid; i < V_; i += 512) { float e = expf(p[i] - m); p[i] = e; s += e; }
#pragma unroll
    for (int o = 16; o; o >>= 1) s += __shfl_xor_sync(0xffffffffu, s, o);
    if (lane == 0) red[w] = s;
    __syncthreads();
    if (tid == 0) {
        float ss = 0.f;
        for (int i = 0; i < 16; i++) ss += red[i];
        bc = 1.f / ss;
    }
    __syncthreads();
    float inv = bc;
    for (int i = tid; i < V_; i += 512) p[i] *= inv;
}

// ---------------------------------------------------------------------------
// Host orchestration
// ---------------------------------------------------------------------------
extern "C" void kernel_launch(void* const* d_in, const int* in_sizes, int n_in,
                              void* d_out, int out_size)
{
    const float* src       = (const float*)d_in[0];
    const int*   trg       = (const int*)  d_in[1];
    const float* Wih_f     = (const float*)d_in[2];
    const float* Whh_f     = (const float*)d_in[3];
    const float* bih_f     = (const float*)d_in[4];
    const float* bhh_f     = (const float*)d_in[5];
    const float* Wih_b     = (const float*)d_in[6];
    const float* Whh_b     = (const float*)d_in[7];
    const float* bih_b     = (const float*)d_in[8];
    const float* bhh_b     = (const float*)d_in[9];
    const float* fcW       = (const float*)d_in[10];
    const float* fcb       = (const float*)d_in[11];
    const float* attn_W    = (const float*)d_in[12];
    const float* attn_b    = (const float*)d_in[13];
    const float* attn_v    = (const float*)d_in[14];
    const float* emb_table = (const float*)d_in[15];
    const float* gru_Wih   = (const float*)d_in[16];
    const float* gru_Whh   = (const float*)d_in[17];
    const float* gru_bih   = (const float*)d_in[18];
    const float* gru_bhh   = (const float*)d_in[19];
    const float* out_W     = (const float*)d_in[20];
    const float* out_b     = (const float*)d_in[21];
    float* out = (float*)d_out;

    void *vp;
    cudaGetSymbolAddress(&vp, g_pre);      float* pre_p      = (float*)vp;
    cudaGetSymbolAddress(&vp, g_enc_out);  float* enc_out_p  = (float*)vp;
    cudaGetSymbolAddress(&vp, g_enc_part); float* enc_part_p = (float*)vp;
    cudaGetSymbolAddress(&vp, g_hcat);     float* hcat_p     = (float*)vp;
    cudaGetSymbolAddress(&vp, g_h);        float* h_p        = (float*)vp;
    cudaGetSymbolAddress(&vp, g_gi_emb);   float* gi_emb_p   = (float*)vp;
    cudaGetSymbolAddress(&vp, g_feat);     float* feat_p     = (float*)vp;
    cudaGetSymbolAddress(&vp, g_bpre);     float* bpre_p     = (float*)vp;
    cudaGetSymbolAddress(&vp, g_A2);       __nv_bfloat16* A2_p    = (__nv_bfloat16*)vp;
    cudaGetSymbolAddress(&vp, g_B2);       __nv_bfloat16* B2_p    = (__nv_bfloat16*)vp;
    cudaGetSymbolAddress(&vp, gA2_src);    __nv_bfloat16* A2src_p = (__nv_bfloat16*)vp;
    cudaGetSymbolAddress(&vp, gB2_pre);    __nv_bfloat16* B2pre_p = (__nv_bfloat16*)vp;
    cudaGetSymbolAddress(&vp, gA2_enc);    __nv_bfloat16* A2enc_p = (__nv_bfloat16*)vp;
    cudaGetSymbolAddress(&vp, gB2_attn);   __nv_bfloat16* B2att_p = (__nv_bfloat16*)vp;
    cudaGetSymbolAddress(&vp, gA2_emb);    __nv_bfloat16* A2emb_p = (__nv_bfloat16*)vp;
    cudaGetSymbolAddress(&vp, gB2_wih);    __nv_bfloat16* B2wih_p = (__nv_bfloat16*)vp;

    cudaFuncSetAttribute(gemm_hmma,
                         cudaFuncAttributeMaxDynamicSharedMemorySize, HMMA_SMEM);

    // launch #4 (ncu capture target) = gemm_hmma(pre)
    cat_bias_k<<<2, 256>>>(bih_f, bih_b);
    splitB2_pre_k<<<dim3(1, 512), 256>>>(Wih_f, Wih_b);
    split2_k<<<dim3(1, 16384), 256>>>(src, C_, 256, 16384, A2src_p);
    // pre = src @ [Wih_f;Wih_b]^T + bias : (16384 x 512), K=256 -> NCH=8
    gemm_hmma<<<dim3(4, 128), 256, HMMA_SMEM>>>(A2src_p, B2pre_p, bpre_p,
                                                pre_p, 512, 512, 8, 0);
    transp_k<<<dim3(256, 2), 256>>>(Whh_f, Whh_b);
    enc_rnn<<<dim3(32, 2), 256>>>(bhh_f, bhh_b);
    // hidden = tanh(hcat @ fcW^T + fcb)
    gemm128<<<dim3(4, 1), 256>>>(hcat_p, 2*E_, fcW, 2*E_, fcb,
                                 h_p, D_, D_, 2*E_, 1);
    // enc_part = enc_out @ W_e^T + attn_b : K=512 -> NCH=16
    split2_k<<<dim3(2, 16384), 256>>>(enc_out_p, 2*E_, 512, 16384, A2enc_p);
    split2_k<<<dim3(2, 512), 256>>>(attn_W + D_, D_ + 2*E_, 512, 512, B2att_p);
    gemm_hmma<<<dim3(4, 128), 256, HMMA_SMEM>>>(A2enc_p, B2att_p, attn_b,
                                                enc_part_p, 512, 512, 16, 0);
    // embeddings + gi_emb = emb @ Wih[:, :EMB]^T : K=256 -> NCH=8
    embed_k<<<T_ * B_, EMB_>>>(trg, emb_table);
    split2_k<<<dim3(1, 4096), 256>>>(feat_p + (D_ + 2*E_), FEAT_, 256, 4096,
                                     A2emb_p);
    split2_k<<<dim3(1, 1536), 256>>>(gru_Wih, EMB_ + 2*E_, 256, 1536, B2wih_p);
    gemm_hmma<<<dim3(12, 32), 256, HMMA_SMEM>>>(A2emb_p, B2wih_p,
                                                (const float*)nullptr,
                                                gi_emb_p, 3*D_, 3*D_, 8, 0);
    // out_W split (independent of decoder)
    split2_k<<<dim3(5, VPAD_), 256>>>(out_W, FEAT_, FEAT_, V_, B2_p);

    // --- decoder loop (4 launches/step; proven R7 config) ---
    for (int t = 0; t < T_; t++) {
        dec_gemm_hq<<<dim3(64, 2), 256>>>(gru_Whh, attn_W);
        attn_fused_k<<<B_, 512>>>(attn_v, t);
        dec_gemm_gi<<<dim3(48, 2), 256>>>(gru_Wih, t);
        gru_k<<<B_, 512>>>(t, gru_bhh, gru_bih);
    }

    // --- feat split + HMMA logits GEMM + softmax : K=1280 -> NCH=40 ---
    split2_k<<<dim3(5, T_ * B_), 256>>>(feat_p, FEAT_, FEAT_, T_ * B_, A2_p);
    gemm_hmma<<<dim3(VPAD_ / 128, (T_ * B_) / 128), 256, HMMA_SMEM>>>(
        A2_p, B2_p, out_b, out, V_, V_, 40, 2);
    softmax_v_k<<<T_ * B_, 512>>>(out);
}